// round 3
// baseline (speedup 1.0000x reference)
#include <cuda_runtime.h>

#define B 256
#define D 128
#define NEG 1024
#define SAMPLES 300000
#define TEMPR 0.07f
#define EPS 1e-12f

__device__ __forceinline__ float warp_sum(float v) {
#pragma unroll
    for (int o = 16; o; o >>= 1) v += __shfl_down_sync(0xffffffffu, v, o);
    return v;
}

// block-wide sum for 512 threads (16 warps), result broadcast
__device__ __forceinline__ float block_sum512(float v, volatile float* sm) {
    int lane = threadIdx.x & 31, w = threadIdx.x >> 5;
    float s = warp_sum(v);
    if (lane == 0) sm[w] = s;
    __syncthreads();
    float r = 0.f;
    if (threadIdx.x == 0) {
#pragma unroll
        for (int i = 0; i < 16; i++) r += sm[i];
        sm[16] = r;
    }
    __syncthreads();
    r = sm[16];
    __syncthreads();
    return r;
}

// block-wide sum for 128 threads (4 warps), result broadcast
__device__ __forceinline__ float block_sum128(float v, volatile float* sm) {
    int lane = threadIdx.x & 31, w = threadIdx.x >> 5;
    float s = warp_sum(v);
    if (lane == 0) sm[w] = s;
    __syncthreads();
    float r = sm[0] + sm[1] + sm[2] + sm[3];
    __syncthreads();
    return r;
}

// int64 vs int32 detection (JAX x64 demotion hedge): values < 3e5, so for
// int64 the hi words of the first 4 elements are all zero.
__device__ __forceinline__ bool is_i64(const void* p) {
    const int* q = (const int*)p;
    return ((q[1] | q[3] | q[5] | q[7]) == 0);
}
__device__ __forceinline__ long long ld_idx(const void* p, long long i, bool is64) {
    return is64 ? ((const long long*)p)[i] : (long long)((const int*)p)[i];
}

// ---------------------------------------------------------------------------
// Fused kernel: 1536 blocks x 512 threads.
//   blockIdx%3==1  -> score block (512 total: batch b = sid/2, half = sid&1)
//   otherwise      -> copy block (1024 total), streaming grid-stride copy
// Interleaving keeps every SM wave a mix of BW-bound copy and latency-bound
// gather work, so HBM stays saturated for the whole kernel.
// ---------------------------------------------------------------------------
__global__ __launch_bounds__(512) void fused_kernel(
    const float* __restrict__ audio_emb, const float* __restrict__ video_emb,
    const float* __restrict__ amem, const float* __restrict__ vmem,
    const void* __restrict__ indices, const void* __restrict__ negs,
    float* __restrict__ out_scores,
    float* __restrict__ out_amem, float* __restrict__ out_vmem) {

    const int bx = blockIdx.x;
    const int t = threadIdx.x;

    if (bx % 3 == 1) {
        // ------------------------- score block -------------------------
        const int sid = bx / 3;             // 0..511
        const int b = sid >> 1;
        const int n0 = (sid & 1) * 512;
        const int lane = t & 31;
        const int w = t >> 5;

        __shared__ float red[17];
        __shared__ __align__(16) float na_s[D];
        __shared__ __align__(16) float nv_s[D];
        __shared__ float sbuf[4][512];

        // self-contained normalize of this batch row (threads<128 hold dims)
        float a = 0.f, v = 0.f;
        if (t < D) { a = audio_emb[b * D + t]; v = video_emb[b * D + t]; }
        float sa = block_sum512(a * a, red);
        float sv = block_sum512(v * v, red);
        if (t < D) {
            na_s[t] = a / fmaxf(sqrtf(sa), EPS);
            nv_s[t] = v / fmaxf(sqrtf(sv), EPS);
        }
        __syncthreads();

        const bool is64i = is_i64(indices);
        const bool is64n = is_i64(negs);
        const long long idx = ld_idx(indices, b, is64i);

        const float4 na4 = *(const float4*)(na_s + lane * 4);
        const float4 nv4 = *(const float4*)(nv_s + lane * 4);

#pragma unroll 2
        for (int i = w; i < 512; i += 16) {
            long long neg = ld_idx(negs, (long long)b * NEG + n0 + i, is64n);
            long long row = neg + (neg >= idx ? 1 : 0);
            const float4 av = *(const float4*)(amem + row * D + lane * 4);
            const float4 vv = *(const float4*)(vmem + row * D + lane * 4);

            float s_aa = av.x * na4.x + av.y * na4.y + av.z * na4.z + av.w * na4.w;
            float s_av = av.x * nv4.x + av.y * nv4.y + av.z * nv4.z + av.w * nv4.w;
            float s_va = vv.x * na4.x + vv.y * na4.y + vv.z * na4.z + vv.w * na4.w;
            float s_vv = vv.x * nv4.x + vv.y * nv4.y + vv.z * nv4.z + vv.w * nv4.w;

#pragma unroll
            for (int o = 16; o; o >>= 1) {
                s_aa += __shfl_down_sync(0xffffffffu, s_aa, o);
                s_av += __shfl_down_sync(0xffffffffu, s_av, o);
                s_va += __shfl_down_sync(0xffffffffu, s_va, o);
                s_vv += __shfl_down_sync(0xffffffffu, s_vv, o);
            }
            if (lane == 0) {
                // [0]=neg_v·na  [1]=neg_a·nv  [2]=neg_a·na  [3]=neg_v·nv
                sbuf[0][i] = s_va;
                sbuf[1][i] = s_av;
                sbuf[2][i] = s_aa;
                sbuf[3][i] = s_vv;
            }
        }
        __syncthreads();

        const long long S = (long long)B * (1 + NEG);
        float* dst = out_scores + (long long)b * (1 + NEG) + 1 + n0;
#pragma unroll
        for (int k = 0; k < 4; k++)
            dst[k * S + t] = sbuf[k][t] / TEMPR;
    } else {
        // ------------------------- copy block --------------------------
        // cid in 0..1023 over the two non-score residues
        const int cid = (bx / 3) * 2 + (bx % 3 == 0 ? 0 : 1);
        const size_t N4 = (size_t)SAMPLES * D / 4;   // 9.6M float4 per array
        const size_t stride = (size_t)1024 * 512;
        const float4* as = (const float4*)amem;
        const float4* vs = (const float4*)vmem;
        float4* ad = (float4*)out_amem;
        float4* vd = (float4*)out_vmem;

        size_t i = (size_t)cid * 512 + t;
        // streaming loads/stores: don't evict gather rows from L2
        for (; i + 3 * stride < N4; i += 4 * stride) {
            float4 x0 = __ldcs(as + i);
            float4 x1 = __ldcs(as + i + stride);
            float4 x2 = __ldcs(as + i + 2 * stride);
            float4 x3 = __ldcs(as + i + 3 * stride);
            __stcs(ad + i, x0);
            __stcs(ad + i + stride, x1);
            __stcs(ad + i + 2 * stride, x2);
            __stcs(ad + i + 3 * stride, x3);
            float4 y0 = __ldcs(vs + i);
            float4 y1 = __ldcs(vs + i + stride);
            float4 y2 = __ldcs(vs + i + 2 * stride);
            float4 y3 = __ldcs(vs + i + 3 * stride);
            __stcs(vd + i, y0);
            __stcs(vd + i + stride, y1);
            __stcs(vd + i + 2 * stride, y2);
            __stcs(vd + i + 3 * stride, y3);
        }
        for (; i < N4; i += stride) {
            __stcs(ad + i, __ldcs(as + i));
            __stcs(vd + i, __ldcs(vs + i));
        }
    }
}

// ---------------------------------------------------------------------------
// Finalize: pos scores + momentum update scattered into the copied memories.
// Duplicate indices resolved deterministically as LAST occurrence wins
// (matching sequential scatter semantics of the reference): block b skips
// its scatter if any b' > b carries the same index.
// ---------------------------------------------------------------------------
__global__ __launch_bounds__(128) void finalize_kernel(
    const float* __restrict__ audio_emb, const float* __restrict__ video_emb,
    const float* __restrict__ amem, const float* __restrict__ vmem,
    const void* __restrict__ indices,
    float* __restrict__ out_scores,
    float* __restrict__ out_amem, float* __restrict__ out_vmem) {
    __shared__ float sm[4];
    const int b = blockIdx.x, t = threadIdx.x;
    const bool is64 = is_i64(indices);

    float a = audio_emb[b * D + t];
    float v = video_emb[b * D + t];
    float sa = block_sum128(a * a, sm);
    float sv = block_sum128(v * v, sm);
    float na = a / fmaxf(sqrtf(sa), EPS);
    float nv = v / fmaxf(sqrtf(sv), EPS);

    long long idx = ld_idx(indices, b, is64);
    float pa = amem[idx * D + t];
    float pv = vmem[idx * D + t];

    float d_apv = block_sum128(na * pv, sm);
    float d_vpa = block_sum128(nv * pa, sm);
    float d_apa = block_sum128(na * pa, sm);
    float d_vpv = block_sum128(nv * pv, sm);
    if (t == 0) {
        const long long S = (long long)B * (1 + NEG);
        out_scores[0 * S + (long long)b * (1 + NEG)] = d_apv / TEMPR;
        out_scores[1 * S + (long long)b * (1 + NEG)] = d_vpa / TEMPR;
        out_scores[2 * S + (long long)b * (1 + NEG)] = d_apa / TEMPR;
        out_scores[3 * S + (long long)b * (1 + NEG)] = d_vpv / TEMPR;
    }

    // deterministic duplicate resolution: last occurrence wins
    bool skip = false;
    for (int bb = b + 1; bb < B; bb++) {
        if (ld_idx(indices, bb, is64) == idx) { skip = true; break; }
    }

    float ma = pa * 0.5f + na * 0.5f;
    float mv = pv * 0.5f + nv * 0.5f;
    float sma = block_sum128(ma * ma, sm);
    float smv = block_sum128(mv * mv, sm);
    if (!skip) {
        out_amem[idx * D + t] = ma / fmaxf(sqrtf(sma), EPS);
        out_vmem[idx * D + t] = mv / fmaxf(sqrtf(smv), EPS);
    }
}

extern "C" void kernel_launch(void* const* d_in, const int* in_sizes, int n_in,
                              void* d_out, int out_size) {
    const float* audio_emb = (const float*)d_in[0];
    const float* video_emb = (const float*)d_in[1];
    const float* amem = (const float*)d_in[2];
    const float* vmem = (const float*)d_in[3];
    const void* indices = d_in[4];
    const void* negs = d_in[5];

    float* out = (float*)d_out;
    float* out_scores = out;                                 // [4,256,1025]
    float* out_amem = out + (size_t)4 * B * (1 + NEG);       // [300000,128]
    float* out_vmem = out_amem + (size_t)SAMPLES * D;        // [300000,128]

    fused_kernel<<<1536, 512>>>(audio_emb, video_emb, amem, vmem, indices,
                                negs, out_scores, out_amem, out_vmem);
    finalize_kernel<<<B, 128>>>(audio_emb, video_emb, amem, vmem, indices,
                                out_scores, out_amem, out_vmem);
}